// round 4
// baseline (speedup 1.0000x reference)
#include <cuda_runtime.h>
#include <math.h>

#define B_    16
#define T_    1024
#define E_    1024
#define H_    16
#define DH_   64
#define MROWS (B_*T_)

typedef unsigned long long u64;

// ---------------- scratch (device globals; no allocation allowed) ----------
__device__ float g_Q [(size_t)MROWS*E_];
__device__ float g_K [(size_t)MROWS*E_];
__device__ float g_V [(size_t)MROWS*E_];
__device__ float g_AO[(size_t)MROWS*E_];

// ---------------- packed f32x2 helpers (FFMA2 path, ptxas won't auto-fuse) -
__device__ __forceinline__ u64 pk2(float lo, float hi) {
    u64 r; asm("mov.b64 %0,{%1,%2};" : "=l"(r) : "f"(lo), "f"(hi)); return r;
}
__device__ __forceinline__ float2 upk2(u64 v) {
    float2 r; asm("mov.b64 {%0,%1},%2;" : "=f"(r.x), "=f"(r.y) : "l"(v)); return r;
}
__device__ __forceinline__ void fma2(u64& d, u64 a, u64 b) {
    asm("fma.rn.f32x2 %0,%1,%2,%0;" : "+l"(d) : "l"(a), "l"(b));
}
__device__ __forceinline__ void mul2(u64& d, u64 a, u64 b) {
    asm("mul.rn.f32x2 %0,%1,%2;" : "=l"(d) : "l"(a), "l"(b));
}

// ---------------- fast exp2 (poly, avoids MUFU throughput wall) ------------
__device__ __forceinline__ float fast_exp2(float x) {
    x = fmaxf(x, -120.0f);                 // inputs are always <= 0
    float t  = x + 12582912.0f;            // round-to-nearest-int trick (2^23*1.5)
    int   ei = __float_as_int(t) - 0x4B400000;
    float f  = x - (t - 12582912.0f);      // f in [-0.5, 0.5]
    float p  = 1.3333558146e-3f;
    p = fmaf(p, f, 9.6181291076e-3f);
    p = fmaf(p, f, 5.5504108665e-2f);
    p = fmaf(p, f, 2.4022650696e-1f);
    p = fmaf(p, f, 6.9314718056e-1f);
    p = fmaf(p, f, 1.0f);
    return p * __int_as_float((ei + 127) << 23);
}

// ---------------- GEMM: C[M,N] = A[M,K] * W[N,K]^T + bias[N] ----------------
// 128x128 tile, BK=16, 256 threads, 8x8 per-thread microtile, f32x2 math.
__global__ void __launch_bounds__(256, 2) gemm_nt_bias(
    const float* __restrict__ A, const float* __restrict__ W,
    const float* __restrict__ bias, float* __restrict__ C,
    int K, int N)
{
    __shared__ float As[16][132];   // [k][m], row = 528B (16B multiple)
    __shared__ float Bs[16][132];   // [k][n]
    const int tid = threadIdx.x;
    const int tr  = tid >> 4;       // 0..15 row group
    const int tc  = tid & 15;       // 0..15 col group
    const size_t arow0 = (size_t)blockIdx.y * 128;
    const size_t brow0 = (size_t)blockIdx.x * 128;

    u64 acc[8][4];                  // 8 rows x 4 column-pairs
#pragma unroll
    for (int i = 0; i < 8; i++)
#pragma unroll
        for (int j = 0; j < 4; j++) acc[i][j] = 0ULL;

    for (int k0 = 0; k0 < K; k0 += 16) {
#pragma unroll
        for (int l = 0; l < 2; l++) {
            int idx = tid + 256 * l;          // 0..511
            int r   = idx >> 2;               // 0..127
            int kq  = (idx & 3) << 2;         // 0,4,8,12
            float4 va = *(const float4*)&A[(arow0 + r) * K + k0 + kq];
            As[kq+0][r] = va.x; As[kq+1][r] = va.y;
            As[kq+2][r] = va.z; As[kq+3][r] = va.w;
            float4 vb = *(const float4*)&W[(brow0 + r) * K + k0 + kq];
            Bs[kq+0][r] = vb.x; Bs[kq+1][r] = vb.y;
            Bs[kq+2][r] = vb.z; Bs[kq+3][r] = vb.w;
        }
        __syncthreads();
#pragma unroll
        for (int kk = 0; kk < 16; kk++) {
            float a[8];
            *(float4*)&a[0] = *(const float4*)&As[kk][tr*8];
            *(float4*)&a[4] = *(const float4*)&As[kk][tr*8+4];
            ulonglong2 b01 = *(const ulonglong2*)&Bs[kk][tc*8];
            ulonglong2 b23 = *(const ulonglong2*)&Bs[kk][tc*8+4];
            u64 b2[4] = {b01.x, b01.y, b23.x, b23.y};
#pragma unroll
            for (int i = 0; i < 8; i++) {
                u64 ad = pk2(a[i], a[i]);
#pragma unroll
                for (int j = 0; j < 4; j++)
                    fma2(acc[i][j], ad, b2[j]);
            }
        }
        __syncthreads();
    }

#pragma unroll
    for (int i = 0; i < 8; i++) {
        size_t crow = arow0 + tr*8 + i;
#pragma unroll
        for (int jp = 0; jp < 4; jp += 2) {
            int col = (int)brow0 + tc*8 + jp*2;
            float2 p0 = upk2(acc[i][jp+0]);
            float2 p1 = upk2(acc[i][jp+1]);
            float4 o;
            o.x = p0.x + bias[col+0];
            o.y = p0.y + bias[col+1];
            o.z = p1.x + bias[col+2];
            o.w = p1.y + bias[col+3];
            *(float4*)&C[crow * N + col] = o;
        }
    }
}

// ---------------- 2D RoPE, applied in-place to Q and K ---------------------
__global__ void rope_kernel(float* __restrict__ Q, float* __restrict__ K,
                            const int* __restrict__ rope_pos)
{
    int idx = blockIdx.x * blockDim.x + threadIdx.x;   // MROWS * 512 pairs
    int row = idx >> 9;
    int p   = idx & 511;
    int col = p << 1;
    int dh  = col & (DH_ - 1);
    int local = dh & 31;
    float pos = (float)rope_pos[row * 2 + (dh >= 32 ? 1 : 0)];
    float fi  = (float)(local >> 1);
    float ang = pos * exp2f(fi * -1.6609640474436811f);
    float s, c;
    sincosf(ang, &s, &c);
    size_t o = (size_t)row * E_ + col;
    float2 q = *(float2*)&Q[o];
    float2 k = *(float2*)&K[o];
    float2 qo, ko;
    qo.x = q.x*c - q.y*s;  qo.y = q.y*c + q.x*s;
    ko.x = k.x*c - k.y*s;  ko.y = k.y*c + k.x*s;
    *(float2*)&Q[o] = qo;
    *(float2*)&K[o] = ko;
}

// ---------------- flash attention: 64-query x 64-key tiles, DH=64 ----------
#define SSTR 68   // smem row stride: 68 floats = 272B = 16*17 (16B-aligned rows)
#define FLASH_SMEM (3 * 64 * SSTR * 4)

__global__ void __launch_bounds__(256, 2) flash_attn(
    const float* __restrict__ Q, const float* __restrict__ K,
    const float* __restrict__ V, float* __restrict__ O)
{
    extern __shared__ float sm[];
    float* Qs  = sm;                 // [d][q] 64xSSTR, pre-scaled by 0.125*log2e
    float* KPs = sm + 64*SSTR;       // K as [d][k]; reused as P [q][k]
    float* Vs  = sm + 2*64*SSTR;     // [k][d]

    const int tid = threadIdx.x;
    const int tx  = tid & 15;        // key/dim group
    const int ty  = tid >> 4;        // query group
    const int q0  = blockIdx.x * 64;
    const size_t base = ((size_t)blockIdx.z * T_) * E_ + (size_t)blockIdx.y * DH_;
    const float qscale = 0.125f * 1.4426950408889634f;   // DH^-0.5 * log2(e)

    // load Q tile transposed & pre-scaled
#pragma unroll
    for (int l = 0; l < 4; l++) {
        int idx = tid + 256 * l;
        int r   = idx >> 4;           // local q
        int dg  = (idx & 15) << 2;    // dim group
        float4 v = *(const float4*)&Q[base + (size_t)(q0 + r) * E_ + dg];
        Qs[(dg+0)*SSTR + r] = v.x * qscale;
        Qs[(dg+1)*SSTR + r] = v.y * qscale;
        Qs[(dg+2)*SSTR + r] = v.z * qscale;
        Qs[(dg+3)*SSTR + r] = v.w * qscale;
    }

    u64 acc2[4][2];                  // 4 query rows x 2 dim-pairs
    float mrow[4], lrow[4];
#pragma unroll
    for (int i = 0; i < 4; i++) {
        mrow[i] = -1e30f; lrow[i] = 0.f;
        acc2[i][0] = 0ULL; acc2[i][1] = 0ULL;
    }

    for (int kt = 0; kt < T_/64; kt++) {
        const size_t kbase = base + (size_t)(kt * 64) * E_;
        __syncthreads();   // previous tile's smem reads done (also covers Qs store at kt=0)
#pragma unroll
        for (int l = 0; l < 4; l++) {
            int idx = tid + 256 * l;
            int r   = idx >> 4;
            int dg  = (idx & 15) << 2;
            float4 kv = *(const float4*)&K[kbase + (size_t)r * E_ + dg];
            KPs[(dg+0)*SSTR + r] = kv.x;
            KPs[(dg+1)*SSTR + r] = kv.y;
            KPs[(dg+2)*SSTR + r] = kv.z;
            KPs[(dg+3)*SSTR + r] = kv.w;
            float4 vv = *(const float4*)&V[kbase + (size_t)r * E_ + dg];
            *(float4*)&Vs[r*SSTR + dg] = vv;
        }
        __syncthreads();

        // S = (Q*scale) . K^T   (log2-domain scores), f32x2 packed
        u64 s2[4][2];
#pragma unroll
        for (int i = 0; i < 4; i++) { s2[i][0] = 0ULL; s2[i][1] = 0ULL; }

#pragma unroll 8
        for (int d = 0; d < 64; d++) {
            float4 a = *(const float4*)&Qs[d*SSTR + ty*4];
            ulonglong2 bb = *(const ulonglong2*)&KPs[d*SSTR + tx*4];
            float av[4] = {a.x, a.y, a.z, a.w};
#pragma unroll
            for (int i = 0; i < 4; i++) {
                u64 ad = pk2(av[i], av[i]);
                fma2(s2[i][0], ad, bb.x);
                fma2(s2[i][1], ad, bb.y);
            }
        }

        // online softmax update (exp2 domain) — scalar
        float s[4][4];
#pragma unroll
        for (int i = 0; i < 4; i++) {
            float2 lo = upk2(s2[i][0]);
            float2 hi = upk2(s2[i][1]);
            s[i][0] = lo.x; s[i][1] = lo.y; s[i][2] = hi.x; s[i][3] = hi.y;
        }
#pragma unroll
        for (int i = 0; i < 4; i++) {
            float mt = fmaxf(fmaxf(s[i][0], s[i][1]), fmaxf(s[i][2], s[i][3]));
#pragma unroll
            for (int off = 8; off >= 1; off >>= 1)
                mt = fmaxf(mt, __shfl_xor_sync(0xffffffffu, mt, off));
            float mnew  = fmaxf(mrow[i], mt);
            float alpha = fast_exp2(mrow[i] - mnew);
            mrow[i] = mnew;
            float r = 0.f;
#pragma unroll
            for (int j = 0; j < 4; j++) {
                float pv = fast_exp2(s[i][j] - mnew);
                s[i][j] = pv;
                r += pv;
            }
#pragma unroll
            for (int off = 8; off >= 1; off >>= 1)
                r += __shfl_xor_sync(0xffffffffu, r, off);
            lrow[i] = lrow[i] * alpha + r;
            u64 al2 = pk2(alpha, alpha);
            mul2(acc2[i][0], acc2[i][0], al2);
            mul2(acc2[i][1], acc2[i][1], al2);
        }

        __syncthreads();   // K reads finished; reuse buffer for P
#pragma unroll
        for (int i = 0; i < 4; i++)
#pragma unroll
            for (int j = 0; j < 4; j++)
                KPs[(ty*4 + i)*SSTR + tx*4 + j] = s[i][j];
        __syncthreads();

        // O += P . V   (f32x2 packed)
#pragma unroll 8
        for (int k = 0; k < 64; k++) {
            ulonglong2 vb = *(const ulonglong2*)&Vs[k*SSTR + tx*4];
            float pa[4];
#pragma unroll
            for (int i = 0; i < 4; i++) pa[i] = KPs[(ty*4 + i)*SSTR + k];
#pragma unroll
            for (int i = 0; i < 4; i++) {
                u64 pd = pk2(pa[i], pa[i]);
                fma2(acc2[i][0], pd, vb.x);
                fma2(acc2[i][1], pd, vb.y);
            }
        }
    }

    // finalize: divide by l, write out
#pragma unroll
    for (int i = 0; i < 4; i++) {
        float inv = 1.0f / lrow[i];
        float2 lo = upk2(acc2[i][0]);
        float2 hi = upk2(acc2[i][1]);
        float4 o;
        o.x = lo.x*inv; o.y = lo.y*inv;
        o.z = hi.x*inv; o.w = hi.y*inv;
        *(float4*)&O[base + (size_t)(q0 + ty*4 + i) * E_ + tx*4] = o;
    }
}

// ---------------- launcher --------------------------------------------------
extern "C" void kernel_launch(void* const* d_in, const int* in_sizes, int n_in,
                              void* d_out, int out_size)
{
    const float* hs       = (const float*)d_in[0];
    const int*   rope_pos = (const int*)  d_in[1];
    const float* Wq = (const float*)d_in[2];
    const float* bq = (const float*)d_in[3];
    const float* Wk = (const float*)d_in[4];
    const float* bk = (const float*)d_in[5];
    const float* Wv = (const float*)d_in[6];
    const float* bv = (const float*)d_in[7];
    const float* Wo = (const float*)d_in[8];
    const float* bo = (const float*)d_in[9];
    float* out = (float*)d_out;

    float *qp, *kp, *vp, *aop;
    cudaGetSymbolAddress((void**)&qp,  g_Q);
    cudaGetSymbolAddress((void**)&kp,  g_K);
    cudaGetSymbolAddress((void**)&vp,  g_V);
    cudaGetSymbolAddress((void**)&aop, g_AO);

    dim3 ggrid(E_/128, MROWS/128);   // (8, 128)

    gemm_nt_bias<<<ggrid, 256>>>(hs, Wq, bq, qp, E_, E_);
    gemm_nt_bias<<<ggrid, 256>>>(hs, Wk, bk, kp, E_, E_);
    gemm_nt_bias<<<ggrid, 256>>>(hs, Wv, bv, vp, E_, E_);

    rope_kernel<<<(MROWS * 512) / 256, 256>>>(qp, kp, rope_pos);

    cudaFuncSetAttribute(flash_attn, cudaFuncAttributeMaxDynamicSharedMemorySize, FLASH_SMEM);
    flash_attn<<<dim3(T_/64, H_, B_), 256, FLASH_SMEM>>>(qp, kp, vp, aop);

    gemm_nt_bias<<<ggrid, 256>>>(aop, Wo, bo, out, E_, E_);
}

// round 5
// speedup vs baseline: 1.0016x; 1.0016x over previous
#include <cuda_runtime.h>
#include <math.h>

#define B_    16
#define T_    1024
#define E_    1024
#define H_    16
#define DH_   64
#define MROWS (B_*T_)

typedef unsigned long long u64;

// ---------------- scratch (device globals; no allocation allowed) ----------
__device__ float g_Q [(size_t)MROWS*E_];
__device__ float g_K [(size_t)MROWS*E_];
__device__ float g_V [(size_t)MROWS*E_];
__device__ float g_AO[(size_t)MROWS*E_];

// ---------------- packed f32x2 helpers (FFMA2 path, ptxas won't auto-fuse) -
__device__ __forceinline__ u64 pk2(float lo, float hi) {
    u64 r; asm("mov.b64 %0,{%1,%2};" : "=l"(r) : "f"(lo), "f"(hi)); return r;
}
__device__ __forceinline__ float2 upk2(u64 v) {
    float2 r; asm("mov.b64 {%0,%1},%2;" : "=f"(r.x), "=f"(r.y) : "l"(v)); return r;
}
__device__ __forceinline__ void fma2(u64& d, u64 a, u64 b) {
    asm("fma.rn.f32x2 %0,%1,%2,%0;" : "+l"(d) : "l"(a), "l"(b));
}
__device__ __forceinline__ void mul2(u64& d, u64 a, u64 b) {
    asm("mul.rn.f32x2 %0,%1,%2;" : "=l"(d) : "l"(a), "l"(b));
}

// ---------------- fast exp2 (poly, avoids MUFU throughput wall) ------------
__device__ __forceinline__ float fast_exp2(float x) {
    x = fmaxf(x, -120.0f);                 // inputs are always <= 0
    float t  = x + 12582912.0f;            // round-to-nearest-int trick (2^23*1.5)
    int   ei = __float_as_int(t) - 0x4B400000;
    float f  = x - (t - 12582912.0f);      // f in [-0.5, 0.5]
    float p  = 1.3333558146e-3f;
    p = fmaf(p, f, 9.6181291076e-3f);
    p = fmaf(p, f, 5.5504108665e-2f);
    p = fmaf(p, f, 2.4022650696e-1f);
    p = fmaf(p, f, 6.9314718056e-1f);
    p = fmaf(p, f, 1.0f);
    return p * __int_as_float((ei + 127) << 23);
}

// ---------------- GEMM: C[M,N] = A[M,K] * W[N,K]^T + bias[N] ----------------
// 128x128 tile, BK=16, 256 threads, 8x8 per-thread microtile, f32x2 math.
__global__ void __launch_bounds__(256, 2) gemm_nt_bias(
    const float* __restrict__ A, const float* __restrict__ W,
    const float* __restrict__ bias, float* __restrict__ C,
    int K, int N)
{
    __shared__ float As[16][132];   // [k][m], row = 528B (16B multiple)
    __shared__ float Bs[16][132];   // [k][n]
    const int tid = threadIdx.x;
    const int tr  = tid >> 4;       // 0..15 row group
    const int tc  = tid & 15;       // 0..15 col group
    const size_t arow0 = (size_t)blockIdx.y * 128;
    const size_t brow0 = (size_t)blockIdx.x * 128;

    u64 acc[8][4];                  // 8 rows x 4 column-pairs
#pragma unroll
    for (int i = 0; i < 8; i++)
#pragma unroll
        for (int j = 0; j < 4; j++) acc[i][j] = 0ULL;

    for (int k0 = 0; k0 < K; k0 += 16) {
#pragma unroll
        for (int l = 0; l < 2; l++) {
            int idx = tid + 256 * l;          // 0..511
            int r   = idx >> 2;               // 0..127
            int kq  = (idx & 3) << 2;         // 0,4,8,12
            float4 va = *(const float4*)&A[(arow0 + r) * K + k0 + kq];
            As[kq+0][r] = va.x; As[kq+1][r] = va.y;
            As[kq+2][r] = va.z; As[kq+3][r] = va.w;
            float4 vb = *(const float4*)&W[(brow0 + r) * K + k0 + kq];
            Bs[kq+0][r] = vb.x; Bs[kq+1][r] = vb.y;
            Bs[kq+2][r] = vb.z; Bs[kq+3][r] = vb.w;
        }
        __syncthreads();
#pragma unroll
        for (int kk = 0; kk < 16; kk++) {
            float a[8];
            *(float4*)&a[0] = *(const float4*)&As[kk][tr*8];
            *(float4*)&a[4] = *(const float4*)&As[kk][tr*8+4];
            ulonglong2 b01 = *(const ulonglong2*)&Bs[kk][tc*8];
            ulonglong2 b23 = *(const ulonglong2*)&Bs[kk][tc*8+4];
            u64 b2[4] = {b01.x, b01.y, b23.x, b23.y};
#pragma unroll
            for (int i = 0; i < 8; i++) {
                u64 ad = pk2(a[i], a[i]);
#pragma unroll
                for (int j = 0; j < 4; j++)
                    fma2(acc[i][j], ad, b2[j]);
            }
        }
        __syncthreads();
    }

#pragma unroll
    for (int i = 0; i < 8; i++) {
        size_t crow = arow0 + tr*8 + i;
#pragma unroll
        for (int jp = 0; jp < 4; jp += 2) {
            int col = (int)brow0 + tc*8 + jp*2;
            float2 p0 = upk2(acc[i][jp+0]);
            float2 p1 = upk2(acc[i][jp+1]);
            float4 o;
            o.x = p0.x + bias[col+0];
            o.y = p0.y + bias[col+1];
            o.z = p1.x + bias[col+2];
            o.w = p1.y + bias[col+3];
            *(float4*)&C[crow * N + col] = o;
        }
    }
}

// ---------------- 2D RoPE, applied in-place to Q and K ---------------------
__global__ void rope_kernel(float* __restrict__ Q, float* __restrict__ K,
                            const int* __restrict__ rope_pos)
{
    int idx = blockIdx.x * blockDim.x + threadIdx.x;   // MROWS * 512 pairs
    int row = idx >> 9;
    int p   = idx & 511;
    int col = p << 1;
    int dh  = col & (DH_ - 1);
    int local = dh & 31;
    float pos = (float)rope_pos[row * 2 + (dh >= 32 ? 1 : 0)];
    float fi  = (float)(local >> 1);
    float ang = pos * exp2f(fi * -1.6609640474436811f);
    float s, c;
    sincosf(ang, &s, &c);
    size_t o = (size_t)row * E_ + col;
    float2 q = *(float2*)&Q[o];
    float2 k = *(float2*)&K[o];
    float2 qo, ko;
    qo.x = q.x*c - q.y*s;  qo.y = q.y*c + q.x*s;
    ko.x = k.x*c - k.y*s;  ko.y = k.y*c + k.x*s;
    *(float2*)&Q[o] = qo;
    *(float2*)&K[o] = ko;
}

// ---------------- flash attention: 64-query x 64-key tiles, DH=64 ----------
#define SSTR 68   // smem row stride: 68 floats = 272B = 16*17 (16B-aligned rows)
#define FLASH_SMEM (3 * 64 * SSTR * 4)

__global__ void __launch_bounds__(256, 2) flash_attn(
    const float* __restrict__ Q, const float* __restrict__ K,
    const float* __restrict__ V, float* __restrict__ O)
{
    extern __shared__ float sm[];
    float* Qs  = sm;                 // [d][q] 64xSSTR, pre-scaled by 0.125*log2e
    float* KPs = sm + 64*SSTR;       // K as [d][k]; reused as P [q][k]
    float* Vs  = sm + 2*64*SSTR;     // [k][d]

    const int tid = threadIdx.x;
    const int tx  = tid & 15;        // key/dim group
    const int ty  = tid >> 4;        // query group
    const int q0  = blockIdx.x * 64;
    const size_t base = ((size_t)blockIdx.z * T_) * E_ + (size_t)blockIdx.y * DH_;
    const float qscale = 0.125f * 1.4426950408889634f;   // DH^-0.5 * log2(e)

    // load Q tile transposed & pre-scaled
#pragma unroll
    for (int l = 0; l < 4; l++) {
        int idx = tid + 256 * l;
        int r   = idx >> 4;           // local q
        int dg  = (idx & 15) << 2;    // dim group
        float4 v = *(const float4*)&Q[base + (size_t)(q0 + r) * E_ + dg];
        Qs[(dg+0)*SSTR + r] = v.x * qscale;
        Qs[(dg+1)*SSTR + r] = v.y * qscale;
        Qs[(dg+2)*SSTR + r] = v.z * qscale;
        Qs[(dg+3)*SSTR + r] = v.w * qscale;
    }

    u64 acc2[4][2];                  // 4 query rows x 2 dim-pairs
    float mrow[4], lrow[4];
#pragma unroll
    for (int i = 0; i < 4; i++) {
        mrow[i] = -1e30f; lrow[i] = 0.f;
        acc2[i][0] = 0ULL; acc2[i][1] = 0ULL;
    }

    for (int kt = 0; kt < T_/64; kt++) {
        const size_t kbase = base + (size_t)(kt * 64) * E_;
        __syncthreads();   // previous tile's smem reads done (also covers Qs store at kt=0)
#pragma unroll
        for (int l = 0; l < 4; l++) {
            int idx = tid + 256 * l;
            int r   = idx >> 4;
            int dg  = (idx & 15) << 2;
            float4 kv = *(const float4*)&K[kbase + (size_t)r * E_ + dg];
            KPs[(dg+0)*SSTR + r] = kv.x;
            KPs[(dg+1)*SSTR + r] = kv.y;
            KPs[(dg+2)*SSTR + r] = kv.z;
            KPs[(dg+3)*SSTR + r] = kv.w;
            float4 vv = *(const float4*)&V[kbase + (size_t)r * E_ + dg];
            *(float4*)&Vs[r*SSTR + dg] = vv;
        }
        __syncthreads();

        // S = (Q*scale) . K^T   (log2-domain scores), f32x2 packed
        u64 s2[4][2];
#pragma unroll
        for (int i = 0; i < 4; i++) { s2[i][0] = 0ULL; s2[i][1] = 0ULL; }

#pragma unroll 8
        for (int d = 0; d < 64; d++) {
            float4 a = *(const float4*)&Qs[d*SSTR + ty*4];
            ulonglong2 bb = *(const ulonglong2*)&KPs[d*SSTR + tx*4];
            float av[4] = {a.x, a.y, a.z, a.w};
#pragma unroll
            for (int i = 0; i < 4; i++) {
                u64 ad = pk2(av[i], av[i]);
                fma2(s2[i][0], ad, bb.x);
                fma2(s2[i][1], ad, bb.y);
            }
        }

        // online softmax update (exp2 domain) — scalar
        float s[4][4];
#pragma unroll
        for (int i = 0; i < 4; i++) {
            float2 lo = upk2(s2[i][0]);
            float2 hi = upk2(s2[i][1]);
            s[i][0] = lo.x; s[i][1] = lo.y; s[i][2] = hi.x; s[i][3] = hi.y;
        }
#pragma unroll
        for (int i = 0; i < 4; i++) {
            float mt = fmaxf(fmaxf(s[i][0], s[i][1]), fmaxf(s[i][2], s[i][3]));
#pragma unroll
            for (int off = 8; off >= 1; off >>= 1)
                mt = fmaxf(mt, __shfl_xor_sync(0xffffffffu, mt, off));
            float mnew  = fmaxf(mrow[i], mt);
            float alpha = fast_exp2(mrow[i] - mnew);
            mrow[i] = mnew;
            float r = 0.f;
#pragma unroll
            for (int j = 0; j < 4; j++) {
                float pv = fast_exp2(s[i][j] - mnew);
                s[i][j] = pv;
                r += pv;
            }
#pragma unroll
            for (int off = 8; off >= 1; off >>= 1)
                r += __shfl_xor_sync(0xffffffffu, r, off);
            lrow[i] = lrow[i] * alpha + r;
            u64 al2 = pk2(alpha, alpha);
            mul2(acc2[i][0], acc2[i][0], al2);
            mul2(acc2[i][1], acc2[i][1], al2);
        }

        __syncthreads();   // K reads finished; reuse buffer for P
#pragma unroll
        for (int i = 0; i < 4; i++)
#pragma unroll
            for (int j = 0; j < 4; j++)
                KPs[(ty*4 + i)*SSTR + tx*4 + j] = s[i][j];
        __syncthreads();

        // O += P . V   (f32x2 packed)
#pragma unroll 8
        for (int k = 0; k < 64; k++) {
            ulonglong2 vb = *(const ulonglong2*)&Vs[k*SSTR + tx*4];
            float pa[4];
#pragma unroll
            for (int i = 0; i < 4; i++) pa[i] = KPs[(ty*4 + i)*SSTR + k];
#pragma unroll
            for (int i = 0; i < 4; i++) {
                u64 pd = pk2(pa[i], pa[i]);
                fma2(acc2[i][0], pd, vb.x);
                fma2(acc2[i][1], pd, vb.y);
            }
        }
    }

    // finalize: divide by l, write out
#pragma unroll
    for (int i = 0; i < 4; i++) {
        float inv = 1.0f / lrow[i];
        float2 lo = upk2(acc2[i][0]);
        float2 hi = upk2(acc2[i][1]);
        float4 o;
        o.x = lo.x*inv; o.y = lo.y*inv;
        o.z = hi.x*inv; o.w = hi.y*inv;
        *(float4*)&O[base + (size_t)(q0 + ty*4 + i) * E_ + tx*4] = o;
    }
}

// ---------------- launcher --------------------------------------------------
extern "C" void kernel_launch(void* const* d_in, const int* in_sizes, int n_in,
                              void* d_out, int out_size)
{
    const float* hs       = (const float*)d_in[0];
    const int*   rope_pos = (const int*)  d_in[1];
    const float* Wq = (const float*)d_in[2];
    const float* bq = (const float*)d_in[3];
    const float* Wk = (const float*)d_in[4];
    const float* bk = (const float*)d_in[5];
    const float* Wv = (const float*)d_in[6];
    const float* bv = (const float*)d_in[7];
    const float* Wo = (const float*)d_in[8];
    const float* bo = (const float*)d_in[9];
    float* out = (float*)d_out;

    float *qp, *kp, *vp, *aop;
    cudaGetSymbolAddress((void**)&qp,  g_Q);
    cudaGetSymbolAddress((void**)&kp,  g_K);
    cudaGetSymbolAddress((void**)&vp,  g_V);
    cudaGetSymbolAddress((void**)&aop, g_AO);

    dim3 ggrid(E_/128, MROWS/128);   // (8, 128)

    gemm_nt_bias<<<ggrid, 256>>>(hs, Wq, bq, qp, E_, E_);
    gemm_nt_bias<<<ggrid, 256>>>(hs, Wk, bk, kp, E_, E_);
    gemm_nt_bias<<<ggrid, 256>>>(hs, Wv, bv, vp, E_, E_);

    rope_kernel<<<(MROWS * 512) / 256, 256>>>(qp, kp, rope_pos);

    cudaFuncSetAttribute(flash_attn, cudaFuncAttributeMaxDynamicSharedMemorySize, FLASH_SMEM);
    flash_attn<<<dim3(T_/64, H_, B_), 256, FLASH_SMEM>>>(qp, kp, vp, aop);

    gemm_nt_bias<<<ggrid, 256>>>(aop, Wo, bo, out, E_, E_);
}

// round 6
// speedup vs baseline: 2.9411x; 2.9363x over previous
#include <cuda_runtime.h>
#include <math.h>

#define B_    16
#define T_    1024
#define E_    1024
#define H_    16
#define DH_   64
#define MROWS (B_*T_)

// ---------------- scratch (device globals; no allocation allowed) ----------
__device__ float g_Q [(size_t)MROWS*E_];
__device__ float g_K [(size_t)MROWS*E_];
__device__ float g_V [(size_t)MROWS*E_];
__device__ float g_AO[(size_t)MROWS*E_];

// ---------------- helpers ---------------------------------------------------
__device__ __forceinline__ unsigned f2tf(float x) {
    unsigned r; asm("cvt.rna.tf32.f32 %0,%1;" : "=r"(r) : "f"(x)); return r;
}
__device__ __forceinline__ float ex2(float x) {
    float r; asm("ex2.approx.ftz.f32 %0,%1;" : "=f"(r) : "f"(x)); return r;
}
__device__ __forceinline__ void mma8(float& d0, float& d1, float& d2, float& d3,
                                     unsigned a0, unsigned a1, unsigned a2, unsigned a3,
                                     unsigned b0, unsigned b1) {
    asm("mma.sync.aligned.m16n8k8.row.col.f32.tf32.tf32.f32 "
        "{%0,%1,%2,%3},{%4,%5,%6,%7},{%8,%9},{%0,%1,%2,%3};"
        : "+f"(d0), "+f"(d1), "+f"(d2), "+f"(d3)
        : "r"(a0), "r"(a1), "r"(a2), "r"(a3), "r"(b0), "r"(b1));
}

// ---------------- GEMM: C[M,N] = A[M,K]*W[N,K]^T + bias, tf32 tensor cores --
// 128x128 block, BK=16, 4 warps, 64x64 warp tile. Smem pitch 20 (=4 mod 32):
// fragment loads (8 rows x 4 cols) hit all 32 banks -> conflict-free.
#define GP 20
__global__ void __launch_bounds__(128, 2) gemm_tc(
    const float* __restrict__ A, const float* __restrict__ W,
    const float* __restrict__ bias, float* __restrict__ C)
{
    __shared__ unsigned As[128*GP];   // tf32 bits, [m][k]
    __shared__ unsigned Bs[128*GP];   // tf32 bits, [n][k]
    const int tid = threadIdx.x, lane = tid & 31, warp = tid >> 5;
    const int ty = lane >> 2, tx = lane & 3;
    const int wm = (warp & 1) * 64, wn = (warp >> 1) * 64;
    const size_t am0 = (size_t)blockIdx.y * 128;
    const size_t bn0 = (size_t)blockIdx.x * 128;

    float d[4][8][4];
#pragma unroll
    for (int mi = 0; mi < 4; mi++)
#pragma unroll
        for (int ni = 0; ni < 8; ni++)
#pragma unroll
            for (int c = 0; c < 4; c++) d[mi][ni][c] = 0.f;

    for (int k0 = 0; k0 < E_; k0 += 16) {
#pragma unroll
        for (int i = 0; i < 4; i++) {
            int f4 = tid + 128 * i;          // 0..511
            int r  = f4 >> 2;                // 0..127
            int kq = (f4 & 3) << 2;          // 0,4,8,12
            float4 va = *(const float4*)&A[(am0 + r) * E_ + k0 + kq];
            uint4 ua = { f2tf(va.x), f2tf(va.y), f2tf(va.z), f2tf(va.w) };
            *(uint4*)&As[r*GP + kq] = ua;
            float4 vb = *(const float4*)&W[(bn0 + r) * E_ + k0 + kq];
            uint4 ub = { f2tf(vb.x), f2tf(vb.y), f2tf(vb.z), f2tf(vb.w) };
            *(uint4*)&Bs[r*GP + kq] = ub;
        }
        __syncthreads();
#pragma unroll
        for (int ks = 0; ks < 2; ks++) {
            unsigned a[4][4], b[8][2];
#pragma unroll
            for (int mi = 0; mi < 4; mi++) {
                int r = wm + mi*16 + ty;
                a[mi][0] = As[ r    *GP + ks*8 + tx    ];
                a[mi][1] = As[(r+8) *GP + ks*8 + tx    ];
                a[mi][2] = As[ r    *GP + ks*8 + tx + 4];
                a[mi][3] = As[(r+8) *GP + ks*8 + tx + 4];
            }
#pragma unroll
            for (int ni = 0; ni < 8; ni++) {
                int n = wn + ni*8 + ty;
                b[ni][0] = Bs[n*GP + ks*8 + tx    ];
                b[ni][1] = Bs[n*GP + ks*8 + tx + 4];
            }
#pragma unroll
            for (int mi = 0; mi < 4; mi++)
#pragma unroll
                for (int ni = 0; ni < 8; ni++)
                    mma8(d[mi][ni][0], d[mi][ni][1], d[mi][ni][2], d[mi][ni][3],
                         a[mi][0], a[mi][1], a[mi][2], a[mi][3],
                         b[ni][0], b[ni][1]);
        }
        __syncthreads();
    }

#pragma unroll
    for (int mi = 0; mi < 4; mi++) {
        size_t r0 = am0 + wm + mi*16 + ty;
#pragma unroll
        for (int ni = 0; ni < 8; ni++) {
            int c = (int)bn0 + wn + ni*8 + 2*tx;
            float bx = bias[c], by = bias[c+1];
            float2 o0 = { d[mi][ni][0] + bx, d[mi][ni][1] + by };
            float2 o1 = { d[mi][ni][2] + bx, d[mi][ni][3] + by };
            *(float2*)&C[ r0      * E_ + c] = o0;
            *(float2*)&C[(r0 + 8) * E_ + c] = o1;
        }
    }
}

// ---------------- 2D RoPE, applied in-place to Q and K ---------------------
__global__ void rope_kernel(float* __restrict__ Q, float* __restrict__ K,
                            const int* __restrict__ rope_pos)
{
    int idx = blockIdx.x * blockDim.x + threadIdx.x;
    int row = idx >> 9;
    int p   = idx & 511;
    int col = p << 1;
    int dh  = col & (DH_ - 1);
    int local = dh & 31;
    float pos = (float)rope_pos[row * 2 + (dh >= 32 ? 1 : 0)];
    float fi  = (float)(local >> 1);
    float ang = pos * exp2f(fi * -1.6609640474436811f);
    float s, c;
    sincosf(ang, &s, &c);
    size_t o = (size_t)row * E_ + col;
    float2 q = *(float2*)&Q[o];
    float2 k = *(float2*)&K[o];
    float2 qo, ko;
    qo.x = q.x*c - q.y*s;  qo.y = q.y*c + q.x*s;
    ko.x = k.x*c - k.y*s;  ko.y = k.y*c + k.x*s;
    *(float2*)&Q[o] = qo;
    *(float2*)&K[o] = ko;
}

// ---------------- flash attention, tf32 tensor cores ------------------------
// Block = 128 queries, 4 warps (32q each). 64-key tiles, 16 iterations.
// Q fragments register-resident. Pitches: K=68 (=4 mod 32), V=72 (=8 mod 32),
// P=68 -- each chosen so its fragment access pattern is bank-conflict-free.
#define KP 68
#define VP 72
#define PP 68
#define SMW_K 0
#define SMW_V (64*KP)                   // 4352
#define SMW_P (64*KP + 64*VP)           // 8960
#define FSM_BYTES ((64*KP + 64*VP + 4*32*PP) * 4)   // 70656 B

__global__ void __launch_bounds__(128, 2) flash_tc(
    const float* __restrict__ Q, const float* __restrict__ K,
    const float* __restrict__ V, float* __restrict__ O)
{
    extern __shared__ unsigned sm[];
    unsigned* Ks = sm + SMW_K;
    unsigned* Vs = sm + SMW_V;
    const int tid = threadIdx.x, lane = tid & 31, warp = tid >> 5;
    const int ty = lane >> 2, tx = lane & 3;
    unsigned* Ps = sm + SMW_P + warp * 32 * PP;
    const int q0 = blockIdx.x * 128 + warp * 32;
    const size_t base = ((size_t)blockIdx.z * T_) * E_ + (size_t)blockIdx.y * DH_;
    const float qs = 0.125f * 1.4426950408889634f;   // DH^-0.5 * log2(e)

    // Q fragments: resident for the whole kernel (2 m-tiles x 8 k-steps x 4)
    unsigned qa[2][8][4];
#pragma unroll
    for (int mi = 0; mi < 2; mi++) {
        const float* qr0 = Q + base + (size_t)(q0 + mi*16 + ty) * E_;
        const float* qr1 = qr0 + 8 * E_;
#pragma unroll
        for (int ks = 0; ks < 8; ks++) {
            qa[mi][ks][0] = f2tf(qr0[ks*8 + tx    ] * qs);
            qa[mi][ks][1] = f2tf(qr1[ks*8 + tx    ] * qs);
            qa[mi][ks][2] = f2tf(qr0[ks*8 + tx + 4] * qs);
            qa[mi][ks][3] = f2tf(qr1[ks*8 + tx + 4] * qs);
        }
    }

    float od[2][8][4];
    float mrow[2][2], lrow[2][2];
#pragma unroll
    for (int mi = 0; mi < 2; mi++) {
        mrow[mi][0] = mrow[mi][1] = -1e30f;
        lrow[mi][0] = lrow[mi][1] = 0.f;
#pragma unroll
        for (int ni = 0; ni < 8; ni++)
#pragma unroll
            for (int c = 0; c < 4; c++) od[mi][ni][c] = 0.f;
    }

    for (int kt = 0; kt < T_/64; kt++) {
        const float* Kg = K + base + (size_t)(kt * 64) * E_;
        const float* Vg = V + base + (size_t)(kt * 64) * E_;
        __syncthreads();   // all warps done reading Ks/Vs/Ps from prev iter
#pragma unroll
        for (int i = 0; i < 8; i++) {
            int f4 = tid + 128 * i;       // 0..1023
            int r  = f4 >> 4;             // 0..63
            int cg = (f4 & 15) << 2;      // 0..60
            float4 kv = *(const float4*)&Kg[(size_t)r * E_ + cg];
            uint4 uk = { f2tf(kv.x), f2tf(kv.y), f2tf(kv.z), f2tf(kv.w) };
            *(uint4*)&Ks[r*KP + cg] = uk;
            float4 vv = *(const float4*)&Vg[(size_t)r * E_ + cg];
            uint4 uv = { f2tf(vv.x), f2tf(vv.y), f2tf(vv.z), f2tf(vv.w) };
            *(uint4*)&Vs[r*VP + cg] = uv;
        }
        __syncthreads();

        // S = Q . K^T  (log2-domain: Q pre-scaled)
        float sd[2][8][4];
#pragma unroll
        for (int mi = 0; mi < 2; mi++)
#pragma unroll
            for (int ni = 0; ni < 8; ni++)
#pragma unroll
                for (int c = 0; c < 4; c++) sd[mi][ni][c] = 0.f;

#pragma unroll
        for (int ks = 0; ks < 8; ks++) {
            unsigned kb[8][2];
#pragma unroll
            for (int ni = 0; ni < 8; ni++) {
                int key = ni*8 + ty;
                kb[ni][0] = Ks[key*KP + ks*8 + tx    ];
                kb[ni][1] = Ks[key*KP + ks*8 + tx + 4];
            }
#pragma unroll
            for (int ni = 0; ni < 8; ni++)
#pragma unroll
                for (int mi = 0; mi < 2; mi++)
                    mma8(sd[mi][ni][0], sd[mi][ni][1], sd[mi][ni][2], sd[mi][ni][3],
                         qa[mi][ks][0], qa[mi][ks][1], qa[mi][ks][2], qa[mi][ks][3],
                         kb[ni][0], kb[ni][1]);
        }

        // online softmax: each thread owns 4 rows (2 mtiles x 2 row-halves),
        // 16 of the 64 key-scores per row; quad (xor 1,2) completes the row.
#pragma unroll
        for (int mi = 0; mi < 2; mi++)
#pragma unroll
            for (int rh = 0; rh < 2; rh++) {
                float mx = -1e30f;
#pragma unroll
                for (int ni = 0; ni < 8; ni++)
                    mx = fmaxf(mx, fmaxf(sd[mi][ni][rh*2], sd[mi][ni][rh*2+1]));
                mx = fmaxf(mx, __shfl_xor_sync(0xffffffffu, mx, 1));
                mx = fmaxf(mx, __shfl_xor_sync(0xffffffffu, mx, 2));
                float mnew  = fmaxf(mrow[mi][rh], mx);
                float alpha = ex2(mrow[mi][rh] - mnew);
                mrow[mi][rh] = mnew;
                float s = 0.f;
#pragma unroll
                for (int ni = 0; ni < 8; ni++) {
                    float p0 = ex2(sd[mi][ni][rh*2    ] - mnew);
                    float p1 = ex2(sd[mi][ni][rh*2 + 1] - mnew);
                    sd[mi][ni][rh*2    ] = p0;
                    sd[mi][ni][rh*2 + 1] = p1;
                    s += p0 + p1;
                }
                s += __shfl_xor_sync(0xffffffffu, s, 1);
                s += __shfl_xor_sync(0xffffffffu, s, 2);
                lrow[mi][rh] = lrow[mi][rh] * alpha + s;
#pragma unroll
                for (int ni = 0; ni < 8; ni++) {
                    od[mi][ni][rh*2    ] *= alpha;
                    od[mi][ni][rh*2 + 1] *= alpha;
                }
            }

        // stage P (D-frag layout -> smem, tf32 bits)
#pragma unroll
        for (int mi = 0; mi < 2; mi++) {
            int r = mi*16 + ty;
#pragma unroll
            for (int ni = 0; ni < 8; ni++) {
                uint2 p0 = { f2tf(sd[mi][ni][0]), f2tf(sd[mi][ni][1]) };
                uint2 p1 = { f2tf(sd[mi][ni][2]), f2tf(sd[mi][ni][3]) };
                *(uint2*)&Ps[ r     *PP + ni*8 + 2*tx] = p0;
                *(uint2*)&Ps[(r + 8)*PP + ni*8 + 2*tx] = p1;
            }
        }
        __syncwarp();

        // O += P . V
#pragma unroll
        for (int ks = 0; ks < 8; ks++) {
            unsigned pa[2][4], vb[8][2];
#pragma unroll
            for (int mi = 0; mi < 2; mi++) {
                int r = mi*16 + ty;
                pa[mi][0] = Ps[ r     *PP + ks*8 + tx    ];
                pa[mi][1] = Ps[(r + 8)*PP + ks*8 + tx    ];
                pa[mi][2] = Ps[ r     *PP + ks*8 + tx + 4];
                pa[mi][3] = Ps[(r + 8)*PP + ks*8 + tx + 4];
            }
#pragma unroll
            for (int ni = 0; ni < 8; ni++) {
                int key = ks*8 + tx;
                vb[ni][0] = Vs[ key     *VP + ni*8 + ty];
                vb[ni][1] = Vs[(key + 4)*VP + ni*8 + ty];
            }
#pragma unroll
            for (int ni = 0; ni < 8; ni++)
#pragma unroll
                for (int mi = 0; mi < 2; mi++)
                    mma8(od[mi][ni][0], od[mi][ni][1], od[mi][ni][2], od[mi][ni][3],
                         pa[mi][0], pa[mi][1], pa[mi][2], pa[mi][3],
                         vb[ni][0], vb[ni][1]);
        }
    }

    // normalize and write O
#pragma unroll
    for (int mi = 0; mi < 2; mi++) {
        float inv0 = 1.0f / lrow[mi][0];
        float inv1 = 1.0f / lrow[mi][1];
        float* o0 = O + base + (size_t)(q0 + mi*16 + ty) * E_;
        float* o1 = o0 + 8 * E_;
#pragma unroll
        for (int ni = 0; ni < 8; ni++) {
            int c = ni*8 + 2*tx;
            float2 w0 = { od[mi][ni][0] * inv0, od[mi][ni][1] * inv0 };
            float2 w1 = { od[mi][ni][2] * inv1, od[mi][ni][3] * inv1 };
            *(float2*)&o0[c] = w0;
            *(float2*)&o1[c] = w1;
        }
    }
}

// ---------------- launcher --------------------------------------------------
extern "C" void kernel_launch(void* const* d_in, const int* in_sizes, int n_in,
                              void* d_out, int out_size)
{
    const float* hs       = (const float*)d_in[0];
    const int*   rope_pos = (const int*)  d_in[1];
    const float* Wq = (const float*)d_in[2];
    const float* bq = (const float*)d_in[3];
    const float* Wk = (const float*)d_in[4];
    const float* bk = (const float*)d_in[5];
    const float* Wv = (const float*)d_in[6];
    const float* bv = (const float*)d_in[7];
    const float* Wo = (const float*)d_in[8];
    const float* bo = (const float*)d_in[9];
    float* out = (float*)d_out;

    float *qp, *kp, *vp, *aop;
    cudaGetSymbolAddress((void**)&qp,  g_Q);
    cudaGetSymbolAddress((void**)&kp,  g_K);
    cudaGetSymbolAddress((void**)&vp,  g_V);
    cudaGetSymbolAddress((void**)&aop, g_AO);

    dim3 ggrid(E_/128, MROWS/128);   // (8, 128)

    gemm_tc<<<ggrid, 128>>>(hs, Wq, bq, qp);
    gemm_tc<<<ggrid, 128>>>(hs, Wk, bk, kp);
    gemm_tc<<<ggrid, 128>>>(hs, Wv, bv, vp);

    rope_kernel<<<(MROWS * 512) / 256, 256>>>(qp, kp, rope_pos);

    cudaFuncSetAttribute(flash_tc, cudaFuncAttributeMaxDynamicSharedMemorySize, FSM_BYTES);
    flash_tc<<<dim3(T_/128, H_, B_), 128, FSM_BYTES>>>(qp, kp, vp, aop);

    gemm_tc<<<ggrid, 128>>>(aop, Wo, bo, out);
}